// round 6
// baseline (speedup 1.0000x reference)
#include <cuda_runtime.h>
#include <cuda_fp16.h>
#include <cstdint>

#define M_TOT 8192
#define N_TOT 11008
#define K_TOT 4096
#define BM 128
#define BN 128
#define BK 64
#define NSTG 4
#define NK (K_TOT / BK)        // 64
#define STAGE_B (BM * BK * 2)  // 16384 bytes per operand tile
#define SMEM_TOTAL (NSTG * 2 * STAGE_B)  // 131072

// fp16 scratch images (no cudaMalloc allowed)
__device__ __align__(256) __half g_xh[(size_t)M_TOT * K_TOT];   // 64 MB
__device__ __align__(256) __half g_wh[(size_t)N_TOT * K_TOT];   // 88 MB

__device__ __forceinline__ uint32_t sw128(uint32_t o) { return o ^ ((o >> 3) & 0x70u); }

// ---------------- prepass: x fp32 -> fp16 ----------------
__global__ void convert_x_kernel(const float* __restrict__ x) {
    int idx = blockIdx.x * blockDim.x + threadIdx.x;   // one 8-vector
    const float4* src = reinterpret_cast<const float4*>(x) + 2 * (size_t)idx;
    float4 a = src[0], b = src[1];
    __half2 h0 = __floats2half2_rn(a.x, a.y), h1 = __floats2half2_rn(a.z, a.w);
    __half2 h2 = __floats2half2_rn(b.x, b.y), h3 = __floats2half2_rn(b.z, b.w);
    uint4 v;
    v.x = *reinterpret_cast<uint32_t*>(&h0); v.y = *reinterpret_cast<uint32_t*>(&h1);
    v.z = *reinterpret_cast<uint32_t*>(&h2); v.w = *reinterpret_cast<uint32_t*>(&h3);
    reinterpret_cast<uint4*>(g_xh)[idx] = v;
}

// ---------------- prepass: W int32 -> fp16 (w*s+z) ----------------
__global__ void dequant_kernel(const int* __restrict__ w, const float* __restrict__ sz) {
    int idx = blockIdx.x * blockDim.x + threadIdx.x;
    int n  = idx >> 9;                 // 512 vec8 per row of K=4096
    int kk = (idx & 511) << 3;
    int g  = kk >> 7;                  // group of 128
    size_t si = ((size_t)g * N_TOT + n) * 2;
    float s = sz[si], z = sz[si + 1];
    const int4* wp = reinterpret_cast<const int4*>(w + (size_t)n * K_TOT + kk);
    int4 w0 = wp[0], w1 = wp[1];
    __half2 h0 = __floats2half2_rn(fmaf((float)w0.x, s, z), fmaf((float)w0.y, s, z));
    __half2 h1 = __floats2half2_rn(fmaf((float)w0.z, s, z), fmaf((float)w0.w, s, z));
    __half2 h2 = __floats2half2_rn(fmaf((float)w1.x, s, z), fmaf((float)w1.y, s, z));
    __half2 h3 = __floats2half2_rn(fmaf((float)w1.z, s, z), fmaf((float)w1.w, s, z));
    uint4 v;
    v.x = *reinterpret_cast<uint32_t*>(&h0); v.y = *reinterpret_cast<uint32_t*>(&h1);
    v.z = *reinterpret_cast<uint32_t*>(&h2); v.w = *reinterpret_cast<uint32_t*>(&h3);
    reinterpret_cast<uint4*>(g_wh)[idx] = v;
}

// ---------------- helpers ----------------
__device__ __forceinline__ uint32_t smem_u32(const void* p) {
    uint32_t a;
    asm("{ .reg .u64 t; cvta.to.shared.u64 t, %1; cvt.u32.u64 %0, t; }" : "=r"(a) : "l"(p));
    return a;
}
__device__ __forceinline__ void cp_async16(uint32_t s, const void* g) {
    asm volatile("cp.async.cg.shared.global [%0], [%1], 16;" :: "r"(s), "l"(g));
}
__device__ __forceinline__ void cp_commit() { asm volatile("cp.async.commit_group;"); }
template <int N>
__device__ __forceinline__ void cp_wait() { asm volatile("cp.async.wait_group %0;" :: "n"(N)); }

__device__ __forceinline__ void ldsm_x4(uint32_t& r0, uint32_t& r1, uint32_t& r2, uint32_t& r3,
                                        uint32_t addr) {
    asm volatile("ldmatrix.sync.aligned.m8n8.x4.shared.b16 {%0,%1,%2,%3}, [%4];"
                 : "=r"(r0), "=r"(r1), "=r"(r2), "=r"(r3) : "r"(addr));
}
__device__ __forceinline__ void mma16816(float* c, const uint32_t* a, uint32_t b0, uint32_t b1) {
    asm volatile("mma.sync.aligned.m16n8k16.row.col.f32.f16.f16.f32 "
                 "{%0,%1,%2,%3}, {%4,%5,%6,%7}, {%8,%9}, {%0,%1,%2,%3};"
                 : "+f"(c[0]), "+f"(c[1]), "+f"(c[2]), "+f"(c[3])
                 : "r"(a[0]), "r"(a[1]), "r"(a[2]), "r"(a[3]), "r"(b0), "r"(b1));
}

// ---------------- GEMM: 128x128 tile, BK=64, 4-stage cp.async, 8 warps ----------------
__global__ __launch_bounds__(256, 1)
void gemm_kernel(const float* __restrict__ bias, float* __restrict__ out) {
    extern __shared__ __align__(1024) char smem[];
    uint32_t sb = smem_u32(smem);
    int tid = threadIdx.x, wid = tid >> 5, lane = tid & 31;
    // M-fastest grid: A (64 MB) stays L2-resident across the whole run
    int tile_m = blockIdx.x & 63;          // 64 M tiles
    int tile_n = blockIdx.x >> 6;          // 86 N tiles
    const size_t m0 = (size_t)tile_m * BM, n0 = (size_t)tile_n * BN;

    const __half* agm = g_xh + m0 * K_TOT;
    const __half* bgm = g_wh + n0 * K_TOT;

    // per-thread load slots: 4 A chunks + 4 B chunks per stage (16B each)
    int lrow = tid >> 3;            // 0..31 base row (x4 iterations -> +32)
    int lcb  = (tid & 7) * 16;      // byte column within 128B row

    auto load_stage = [&](int kt, int st) {
        uint32_t sa = sb + st * (2 * STAGE_B);
        uint32_t sbB = sa + STAGE_B;
        const __half* ag = agm + (size_t)kt * BK;
        const __half* bg = bgm + (size_t)kt * BK;
#pragma unroll
        for (int i = 0; i < 4; i++) {
            int r = lrow + i * 32;
            cp_async16(sa  + sw128(r * 128 + lcb), (const char*)(ag + (size_t)r * K_TOT) + lcb);
            cp_async16(sbB + sw128(r * 128 + lcb), (const char*)(bg + (size_t)r * K_TOT) + lcb);
        }
        cp_commit();
    };

    // prologue
    for (int st = 0; st < NSTG - 1; st++) load_stage(st, st);

    int wm = wid & 1, wn = wid >> 1;       // warp tile 64(m) x 32(n)
    float acc[4][4][4];
#pragma unroll
    for (int i = 0; i < 4; i++)
#pragma unroll
        for (int j = 0; j < 4; j++)
#pragma unroll
            for (int t = 0; t < 4; t++) acc[i][j][t] = 0.f;

    // ldmatrix lane address components
    int a_r = wm * 64 + (lane & 15);             // + mi*16
    int a_c = (lane >> 4) * 16;                  // byte offset (+ s*32)
    int b_r = wn * 32 + ((lane >> 4) << 3) + (lane & 7);  // + nh*16
    int b_c = ((lane >> 3) & 1) * 16;            // byte offset (+ s*32)

    for (int kt = 0; kt < NK; kt++) {
        cp_wait<NSTG - 2>();
        __syncthreads();
        if (kt + NSTG - 1 < NK) load_stage(kt + NSTG - 1, (kt + NSTG - 1) % NSTG);
        else cp_commit();

        uint32_t sa = sb + (kt % NSTG) * (2 * STAGE_B);
        uint32_t sbB = sa + STAGE_B;
#pragma unroll
        for (int s = 0; s < 4; s++) {
            uint32_t af[4][4];
#pragma unroll
            for (int mi = 0; mi < 4; mi++)
                ldsm_x4(af[mi][0], af[mi][1], af[mi][2], af[mi][3],
                        sa + sw128((a_r + mi * 16) * 128 + s * 32 + a_c));
            uint32_t bf[4][2];
#pragma unroll
            for (int nh = 0; nh < 2; nh++) {
                uint32_t r0, r1, r2, r3;
                ldsm_x4(r0, r1, r2, r3,
                        sbB + sw128((b_r + nh * 16) * 128 + s * 32 + b_c));
                bf[nh * 2][0] = r0; bf[nh * 2][1] = r1;
                bf[nh * 2 + 1][0] = r2; bf[nh * 2 + 1][1] = r3;
            }
#pragma unroll
            for (int mi = 0; mi < 4; mi++)
#pragma unroll
                for (int ni = 0; ni < 4; ni++)
                    mma16816(acc[mi][ni], af[mi], bf[ni][0], bf[ni][1]);
        }
        __syncthreads();
    }
    cp_wait<0>();

    // epilogue: acc lane layout: c0,c1 @ (row=lane/4, col=(lane%4)*2), c2,c3 @ row+8
    size_t mw = m0 + wm * 64 + (lane >> 2);
    size_t nw = n0 + wn * 32 + (lane & 3) * 2;
#pragma unroll
    for (int mi = 0; mi < 4; mi++) {
#pragma unroll
        for (int ni = 0; ni < 4; ni++) {
            size_t n = nw + ni * 8;
            float b0 = __ldg(bias + n), b1 = __ldg(bias + n + 1);
            float* p0 = out + (mw + mi * 16) * N_TOT + n;
            float* p1 = out + (mw + mi * 16 + 8) * N_TOT + n;
            float2 v0 = {acc[mi][ni][0] + b0, acc[mi][ni][1] + b1};
            float2 v1 = {acc[mi][ni][2] + b0, acc[mi][ni][3] + b1};
            *reinterpret_cast<float2*>(p0) = v0;
            *reinterpret_cast<float2*>(p1) = v1;
        }
    }
}

// ---------------- launch ----------------
extern "C" void kernel_launch(void* const* d_in, const int* in_sizes, int n_in,
                              void* d_out, int out_size) {
    const float* x    = (const float*)d_in[0];
    const int*   w    = (const int*)d_in[1];
    const float* sz   = (const float*)d_in[2];
    const float* bias = (const float*)d_in[3];
    float* out = (float*)d_out;

    cudaFuncSetAttribute(gemm_kernel, cudaFuncAttributeMaxDynamicSharedMemorySize, SMEM_TOTAL);

    convert_x_kernel<<<(M_TOT * K_TOT / 8) / 256, 256>>>(x);
    dequant_kernel<<<(N_TOT * K_TOT / 8) / 256, 256>>>(w, sz);
    gemm_kernel<<<(M_TOT / BM) * (N_TOT / BN), 256, SMEM_TOTAL>>>(bias, out);
}

// round 7
// speedup vs baseline: 1.1040x; 1.1040x over previous
#include <cuda_runtime.h>
#include <cuda_fp16.h>
#include <cstdint>

#define M_TOT 8192
#define N_TOT 11008
#define K_TOT 4096
#define BM 256
#define BN 128
#define BK 64
#define NSTG 4
#define NK (K_TOT / BK)            // 64
#define A_STAGE_B (BM * BK * 2)    // 32768
#define B_STAGE_B (BN * BK * 2)    // 16384
#define STAGE_B   (A_STAGE_B + B_STAGE_B)   // 49152
#define SMEM_TOTAL (NSTG * STAGE_B)         // 196608

// fp16 scratch images (no cudaMalloc allowed)
__device__ __align__(256) __half g_xh[(size_t)M_TOT * K_TOT];   // 64 MB
__device__ __align__(256) __half g_wh[(size_t)N_TOT * K_TOT];   // 88 MB

__device__ __forceinline__ uint32_t sw128(uint32_t o) { return o ^ ((o >> 3) & 0x70u); }

// ---------------- prepass: x fp32 -> fp16 ----------------
__global__ void convert_x_kernel(const float* __restrict__ x) {
    int idx = blockIdx.x * blockDim.x + threadIdx.x;   // one 8-vector
    const float4* src = reinterpret_cast<const float4*>(x) + 2 * (size_t)idx;
    float4 a = src[0], b = src[1];
    __half2 h0 = __floats2half2_rn(a.x, a.y), h1 = __floats2half2_rn(a.z, a.w);
    __half2 h2 = __floats2half2_rn(b.x, b.y), h3 = __floats2half2_rn(b.z, b.w);
    uint4 v;
    v.x = *reinterpret_cast<uint32_t*>(&h0); v.y = *reinterpret_cast<uint32_t*>(&h1);
    v.z = *reinterpret_cast<uint32_t*>(&h2); v.w = *reinterpret_cast<uint32_t*>(&h3);
    reinterpret_cast<uint4*>(g_xh)[idx] = v;
}

// ---------------- prepass: W int32 -> fp16 (w*s+z) ----------------
__global__ void dequant_kernel(const int* __restrict__ w, const float* __restrict__ sz) {
    int idx = blockIdx.x * blockDim.x + threadIdx.x;
    int n  = idx >> 9;                 // 512 vec8 per row of K=4096
    int kk = (idx & 511) << 3;
    int g  = kk >> 7;                  // group of 128
    size_t si = ((size_t)g * N_TOT + n) * 2;
    float s = sz[si], z = sz[si + 1];
    const int4* wp = reinterpret_cast<const int4*>(w + (size_t)n * K_TOT + kk);
    int4 w0 = wp[0], w1 = wp[1];
    __half2 h0 = __floats2half2_rn(fmaf((float)w0.x, s, z), fmaf((float)w0.y, s, z));
    __half2 h1 = __floats2half2_rn(fmaf((float)w0.z, s, z), fmaf((float)w0.w, s, z));
    __half2 h2 = __floats2half2_rn(fmaf((float)w1.x, s, z), fmaf((float)w1.y, s, z));
    __half2 h3 = __floats2half2_rn(fmaf((float)w1.z, s, z), fmaf((float)w1.w, s, z));
    uint4 v;
    v.x = *reinterpret_cast<uint32_t*>(&h0); v.y = *reinterpret_cast<uint32_t*>(&h1);
    v.z = *reinterpret_cast<uint32_t*>(&h2); v.w = *reinterpret_cast<uint32_t*>(&h3);
    reinterpret_cast<uint4*>(g_wh)[idx] = v;
}

// ---------------- helpers ----------------
__device__ __forceinline__ uint32_t smem_u32(const void* p) {
    uint32_t a;
    asm("{ .reg .u64 t; cvta.to.shared.u64 t, %1; cvt.u32.u64 %0, t; }" : "=r"(a) : "l"(p));
    return a;
}
__device__ __forceinline__ void cp_async16(uint32_t s, const void* g) {
    asm volatile("cp.async.cg.shared.global [%0], [%1], 16;" :: "r"(s), "l"(g));
}
__device__ __forceinline__ void cp_commit() { asm volatile("cp.async.commit_group;"); }
template <int N>
__device__ __forceinline__ void cp_wait() { asm volatile("cp.async.wait_group %0;" :: "n"(N)); }

__device__ __forceinline__ void ldsm_x4(uint32_t& r0, uint32_t& r1, uint32_t& r2, uint32_t& r3,
                                        uint32_t addr) {
    asm volatile("ldmatrix.sync.aligned.m8n8.x4.shared.b16 {%0,%1,%2,%3}, [%4];"
                 : "=r"(r0), "=r"(r1), "=r"(r2), "=r"(r3) : "r"(addr));
}
__device__ __forceinline__ void mma16816(float* c, const uint32_t* a, uint32_t b0, uint32_t b1) {
    asm volatile("mma.sync.aligned.m16n8k16.row.col.f32.f16.f16.f32 "
                 "{%0,%1,%2,%3}, {%4,%5,%6,%7}, {%8,%9}, {%0,%1,%2,%3};"
                 : "+f"(c[0]), "+f"(c[1]), "+f"(c[2]), "+f"(c[3])
                 : "r"(a[0]), "r"(a[1]), "r"(a[2]), "r"(a[3]), "r"(b0), "r"(b1));
}

// ---------------- GEMM: 256x128 CTA, 64x64 warp tiles, BK=64, 4-stage cp.async ----------------
__global__ __launch_bounds__(256, 1)
void gemm_kernel(const float* __restrict__ bias, float* __restrict__ out) {
    extern __shared__ __align__(1024) char smem[];
    uint32_t sb = smem_u32(smem);
    int tid = threadIdx.x, wid = tid >> 5, lane = tid & 31;
    // M-fastest grid: A (64 MB) stays L2-resident
    int tile_m = blockIdx.x & 31;          // 32 M tiles of 256
    int tile_n = blockIdx.x >> 5;          // 86 N tiles of 128
    const size_t m0 = (size_t)tile_m * BM, n0 = (size_t)tile_n * BN;

    const __half* agm = g_xh + m0 * K_TOT;
    const __half* bgm = g_wh + n0 * K_TOT;

    int lrow = tid >> 3;            // 0..31 base row
    int lcb  = (tid & 7) * 16;      // byte column within 128B row

    auto load_stage = [&](int kt, int st) {
        uint32_t sa = sb + st * STAGE_B;
        uint32_t sbB = sa + A_STAGE_B;
        const __half* ag = agm + (size_t)kt * BK;
        const __half* bg = bgm + (size_t)kt * BK;
#pragma unroll
        for (int i = 0; i < 8; i++) {      // A: 256 rows
            int r = lrow + i * 32;
            cp_async16(sa + sw128(r * 128 + lcb), (const char*)(ag + (size_t)r * K_TOT) + lcb);
        }
#pragma unroll
        for (int i = 0; i < 4; i++) {      // B: 128 rows
            int r = lrow + i * 32;
            cp_async16(sbB + sw128(r * 128 + lcb), (const char*)(bg + (size_t)r * K_TOT) + lcb);
        }
        cp_commit();
    };

    // prologue
    for (int st = 0; st < NSTG - 1; st++) load_stage(st, st);

    int wm = wid & 3, wn = wid >> 2;       // 4(m) x 2(n) warps, each 64x64
    float acc[4][8][4];
#pragma unroll
    for (int i = 0; i < 4; i++)
#pragma unroll
        for (int j = 0; j < 8; j++)
#pragma unroll
            for (int t = 0; t < 4; t++) acc[i][j][t] = 0.f;

    // ldmatrix lane address components
    int a_r = wm * 64 + (lane & 15);                       // + mi*16
    int a_c = (lane >> 4) * 16;                            // + s*32
    int b_r = wn * 64 + ((lane >> 4) << 3) + (lane & 7);   // + nh*16
    int b_c = ((lane >> 3) & 1) * 16;                      // + s*32

    for (int kt = 0; kt < NK; kt++) {
        cp_wait<NSTG - 2>();
        __syncthreads();
        if (kt + NSTG - 1 < NK) load_stage(kt + NSTG - 1, (kt + NSTG - 1) % NSTG);
        else cp_commit();

        uint32_t sa = sb + (kt % NSTG) * STAGE_B;
        uint32_t sbB = sa + A_STAGE_B;
#pragma unroll
        for (int s = 0; s < 4; s++) {
            uint32_t af[4][4];
#pragma unroll
            for (int mi = 0; mi < 4; mi++)
                ldsm_x4(af[mi][0], af[mi][1], af[mi][2], af[mi][3],
                        sa + sw128((a_r + mi * 16) * 128 + s * 32 + a_c));
            uint32_t bf[8][2];
#pragma unroll
            for (int nh = 0; nh < 4; nh++) {
                uint32_t r0, r1, r2, r3;
                ldsm_x4(r0, r1, r2, r3,
                        sbB + sw128((b_r + nh * 16) * 128 + s * 32 + b_c));
                bf[nh * 2][0] = r0; bf[nh * 2][1] = r1;
                bf[nh * 2 + 1][0] = r2; bf[nh * 2 + 1][1] = r3;
            }
#pragma unroll
            for (int mi = 0; mi < 4; mi++)
#pragma unroll
                for (int ni = 0; ni < 8; ni++)
                    mma16816(acc[mi][ni], af[mi], bf[ni][0], bf[ni][1]);
        }
        // no trailing sync needed: next iteration's top sync orders
        // compute(kt) completion before stage (kt) slot is overwritten
    }
    cp_wait<0>();

    // epilogue: c0,c1 @ (row=lane/4, col=(lane%4)*2), c2,c3 @ row+8
    size_t mw = m0 + wm * 64 + (lane >> 2);
    size_t nw = n0 + wn * 64 + (lane & 3) * 2;
#pragma unroll
    for (int mi = 0; mi < 4; mi++) {
#pragma unroll
        for (int ni = 0; ni < 8; ni++) {
            size_t n = nw + ni * 8;
            float b0 = __ldg(bias + n), b1 = __ldg(bias + n + 1);
            float* p0 = out + (mw + mi * 16) * N_TOT + n;
            float* p1 = out + (mw + mi * 16 + 8) * N_TOT + n;
            float2 v0 = {acc[mi][ni][0] + b0, acc[mi][ni][1] + b1};
            float2 v1 = {acc[mi][ni][2] + b0, acc[mi][ni][3] + b1};
            *reinterpret_cast<float2*>(p0) = v0;
            *reinterpret_cast<float2*>(p1) = v1;
        }
    }
}

// ---------------- launch ----------------
extern "C" void kernel_launch(void* const* d_in, const int* in_sizes, int n_in,
                              void* d_out, int out_size) {
    const float* x    = (const float*)d_in[0];
    const int*   w    = (const int*)d_in[1];
    const float* sz   = (const float*)d_in[2];
    const float* bias = (const float*)d_in[3];
    float* out = (float*)d_out;

    cudaFuncSetAttribute(gemm_kernel, cudaFuncAttributeMaxDynamicSharedMemorySize, SMEM_TOTAL);

    convert_x_kernel<<<(M_TOT * K_TOT / 8) / 256, 256>>>(x);
    dequant_kernel<<<(N_TOT * K_TOT / 8) / 256, 256>>>(w, sz);
    gemm_kernel<<<(M_TOT / BM) * (N_TOT / BN), 256, SMEM_TOTAL>>>(bias, out);
}

// round 8
// speedup vs baseline: 1.1285x; 1.0222x over previous
#include <cuda_runtime.h>
#include <cuda_fp16.h>
#include <cstdint>

#define M_TOT 8192
#define N_TOT 11008
#define K_TOT 4096
#define BM 256
#define BN 128
#define BK 64
#define NSTG 4
#define NK (K_TOT / BK)            // 64
#define A_STAGE_B (BM * BK * 2)    // 32768
#define B_STAGE_B (BN * BK * 2)    // 16384
#define STAGE_B   (A_STAGE_B + B_STAGE_B)   // 49152
#define SMEM_TOTAL (NSTG * STAGE_B)         // 196608

// fp16 scratch images (no cudaMalloc allowed)
__device__ __align__(256) __half g_xh[(size_t)M_TOT * K_TOT];   // 64 MB
__device__ __align__(256) __half g_wh[(size_t)N_TOT * K_TOT];   // 88 MB

__device__ __forceinline__ uint32_t sw128(uint32_t o) { return o ^ ((o >> 3) & 0x70u); }

// ---------------- prepass: x fp32 -> fp16 ----------------
__global__ void convert_x_kernel(const float* __restrict__ x) {
    int idx = blockIdx.x * blockDim.x + threadIdx.x;   // one 8-vector
    const float4* src = reinterpret_cast<const float4*>(x) + 2 * (size_t)idx;
    float4 a = src[0], b = src[1];
    __half2 h0 = __floats2half2_rn(a.x, a.y), h1 = __floats2half2_rn(a.z, a.w);
    __half2 h2 = __floats2half2_rn(b.x, b.y), h3 = __floats2half2_rn(b.z, b.w);
    uint4 v;
    v.x = *reinterpret_cast<uint32_t*>(&h0); v.y = *reinterpret_cast<uint32_t*>(&h1);
    v.z = *reinterpret_cast<uint32_t*>(&h2); v.w = *reinterpret_cast<uint32_t*>(&h3);
    reinterpret_cast<uint4*>(g_xh)[idx] = v;
}

// ---------------- prepass: W int32 -> fp16 (w*s+z) ----------------
__global__ void dequant_kernel(const int* __restrict__ w, const float* __restrict__ sz) {
    int idx = blockIdx.x * blockDim.x + threadIdx.x;
    int n  = idx >> 9;                 // 512 vec8 per row of K=4096
    int kk = (idx & 511) << 3;
    int g  = kk >> 7;                  // group of 128
    size_t si = ((size_t)g * N_TOT + n) * 2;
    float s = sz[si], z = sz[si + 1];
    const int4* wp = reinterpret_cast<const int4*>(w + (size_t)n * K_TOT + kk);
    int4 w0 = wp[0], w1 = wp[1];
    __half2 h0 = __floats2half2_rn(fmaf((float)w0.x, s, z), fmaf((float)w0.y, s, z));
    __half2 h1 = __floats2half2_rn(fmaf((float)w0.z, s, z), fmaf((float)w0.w, s, z));
    __half2 h2 = __floats2half2_rn(fmaf((float)w1.x, s, z), fmaf((float)w1.y, s, z));
    __half2 h3 = __floats2half2_rn(fmaf((float)w1.z, s, z), fmaf((float)w1.w, s, z));
    uint4 v;
    v.x = *reinterpret_cast<uint32_t*>(&h0); v.y = *reinterpret_cast<uint32_t*>(&h1);
    v.z = *reinterpret_cast<uint32_t*>(&h2); v.w = *reinterpret_cast<uint32_t*>(&h3);
    reinterpret_cast<uint4*>(g_wh)[idx] = v;
}

// ---------------- helpers ----------------
__device__ __forceinline__ uint32_t smem_u32(const void* p) {
    uint32_t a;
    asm("{ .reg .u64 t; cvta.to.shared.u64 t, %1; cvt.u32.u64 %0, t; }" : "=r"(a) : "l"(p));
    return a;
}
__device__ __forceinline__ void cp_async16(uint32_t s, const void* g) {
    asm volatile("cp.async.cg.shared.global [%0], [%1], 16;" :: "r"(s), "l"(g));
}
__device__ __forceinline__ void cp_commit() { asm volatile("cp.async.commit_group;"); }
template <int N>
__device__ __forceinline__ void cp_wait() { asm volatile("cp.async.wait_group %0;" :: "n"(N)); }

__device__ __forceinline__ void ldsm_x4(uint32_t& r0, uint32_t& r1, uint32_t& r2, uint32_t& r3,
                                        uint32_t addr) {
    asm volatile("ldmatrix.sync.aligned.m8n8.x4.shared.b16 {%0,%1,%2,%3}, [%4];"
                 : "=r"(r0), "=r"(r1), "=r"(r2), "=r"(r3) : "r"(addr));
}
__device__ __forceinline__ void mma16816(float* c, const uint32_t* a, uint32_t b0, uint32_t b1) {
    asm volatile("mma.sync.aligned.m16n8k16.row.col.f32.f16.f16.f32 "
                 "{%0,%1,%2,%3}, {%4,%5,%6,%7}, {%8,%9}, {%0,%1,%2,%3};"
                 : "+f"(c[0]), "+f"(c[1]), "+f"(c[2]), "+f"(c[3])
                 : "r"(a[0]), "r"(a[1]), "r"(a[2]), "r"(a[3]), "r"(b0), "r"(b1));
}
__device__ __forceinline__ void st_cs_v2(float* p, float a, float b) {
    asm volatile("st.global.cs.v2.f32 [%0], {%1,%2};" :: "l"(p), "f"(a), "f"(b) : "memory");
}

// ---------------- GEMM: 256x128 CTA, 64x64 warp tiles, frag double-buffering ----------------
__global__ __launch_bounds__(256, 1)
void gemm_kernel(const float* __restrict__ bias, float* __restrict__ out) {
    extern __shared__ __align__(1024) char smem[];
    uint32_t sb = smem_u32(smem);
    int tid = threadIdx.x, wid = tid >> 5, lane = tid & 31;
    // M-fastest grid: A (64 MB) stays L2-resident
    int tile_m = blockIdx.x & 31;          // 32 M tiles of 256
    int tile_n = blockIdx.x >> 5;          // 86 N tiles of 128
    const size_t m0 = (size_t)tile_m * BM, n0 = (size_t)tile_n * BN;

    const __half* agm = g_xh + m0 * K_TOT;
    const __half* bgm = g_wh + n0 * K_TOT;

    int lrow = tid >> 3;            // 0..31 base row
    int lcb  = (tid & 7) * 16;      // byte column within 128B row

    auto load_stage = [&](int kt, int st) {
        uint32_t sa = sb + st * STAGE_B;
        uint32_t sbB = sa + A_STAGE_B;
        const __half* ag = agm + (size_t)kt * BK;
        const __half* bg = bgm + (size_t)kt * BK;
#pragma unroll
        for (int i = 0; i < 8; i++) {      // A: 256 rows
            int r = lrow + i * 32;
            cp_async16(sa + sw128(r * 128 + lcb), (const char*)(ag + (size_t)r * K_TOT) + lcb);
        }
#pragma unroll
        for (int i = 0; i < 4; i++) {      // B: 128 rows
            int r = lrow + i * 32;
            cp_async16(sbB + sw128(r * 128 + lcb), (const char*)(bg + (size_t)r * K_TOT) + lcb);
        }
        cp_commit();
    };

    // prologue
    for (int st = 0; st < NSTG - 1; st++) load_stage(st, st);

    int wm = wid & 3, wn = wid >> 2;       // 4(m) x 2(n) warps, each 64x64
    float acc[4][8][4];
#pragma unroll
    for (int i = 0; i < 4; i++)
#pragma unroll
        for (int j = 0; j < 8; j++)
#pragma unroll
            for (int t = 0; t < 4; t++) acc[i][j][t] = 0.f;

    // ldmatrix lane address components
    int a_r = wm * 64 + (lane & 15);                       // + mi*16
    int a_c = (lane >> 4) * 16;                            // + s*32
    int b_r = wn * 64 + ((lane >> 4) << 3) + (lane & 7);   // + nh*16
    int b_c = ((lane >> 3) & 1) * 16;                      // + s*32

    uint32_t af[2][4][4];
    uint32_t bf[2][8][2];

    auto load_frags = [&](uint32_t sa, uint32_t sbB, int s, int buf) {
#pragma unroll
        for (int mi = 0; mi < 4; mi++)
            ldsm_x4(af[buf][mi][0], af[buf][mi][1], af[buf][mi][2], af[buf][mi][3],
                    sa + sw128((a_r + mi * 16) * 128 + s * 32 + a_c));
#pragma unroll
        for (int nh = 0; nh < 4; nh++) {
            uint32_t r0, r1, r2, r3;
            ldsm_x4(r0, r1, r2, r3,
                    sbB + sw128((b_r + nh * 16) * 128 + s * 32 + b_c));
            bf[buf][nh * 2][0] = r0; bf[buf][nh * 2][1] = r1;
            bf[buf][nh * 2 + 1][0] = r2; bf[buf][nh * 2 + 1][1] = r3;
        }
    };

    for (int kt = 0; kt < NK; kt++) {
        cp_wait<NSTG - 2>();
        __syncthreads();

        uint32_t sa = sb + (kt % NSTG) * STAGE_B;
        uint32_t sbB = sa + A_STAGE_B;

        // frags for s=0 first (critical path), then next stage's bulk loads
        load_frags(sa, sbB, 0, 0);
        if (kt + NSTG - 1 < NK) load_stage(kt + NSTG - 1, (kt + NSTG - 1) % NSTG);
        else cp_commit();   // keep wait_group accounting aligned in the tail

#pragma unroll
        for (int s = 0; s < 4; s++) {
            int cur = s & 1;
            if (s < 3) load_frags(sa, sbB, s + 1, cur ^ 1);
#pragma unroll
            for (int mi = 0; mi < 4; mi++)
#pragma unroll
                for (int ni = 0; ni < 8; ni++)
                    mma16816(acc[mi][ni], af[cur][mi], bf[cur][ni][0], bf[cur][ni][1]);
        }
        // next iteration's top sync orders compute before slot reuse
    }
    cp_wait<0>();

    // epilogue: c0,c1 @ (row=lane/4, col=(lane%4)*2), c2,c3 @ row+8; streaming stores
    size_t mw = m0 + wm * 64 + (lane >> 2);
    size_t nw = n0 + wn * 64 + (lane & 3) * 2;
#pragma unroll
    for (int mi = 0; mi < 4; mi++) {
#pragma unroll
        for (int ni = 0; ni < 8; ni++) {
            size_t n = nw + ni * 8;
            float b0 = __ldg(bias + n), b1 = __ldg(bias + n + 1);
            float* p0 = out + (mw + mi * 16) * N_TOT + n;
            float* p1 = out + (mw + mi * 16 + 8) * N_TOT + n;
            st_cs_v2(p0, acc[mi][ni][0] + b0, acc[mi][ni][1] + b1);
            st_cs_v2(p1, acc[mi][ni][2] + b0, acc[mi][ni][3] + b1);
        }
    }
}

// ---------------- launch ----------------
extern "C" void kernel_launch(void* const* d_in, const int* in_sizes, int n_in,
                              void* d_out, int out_size) {
    const float* x    = (const float*)d_in[0];
    const int*   w    = (const int*)d_in[1];
    const float* sz   = (const float*)d_in[2];
    const float* bias = (const float*)d_in[3];
    float* out = (float*)d_out;

    cudaFuncSetAttribute(gemm_kernel, cudaFuncAttributeMaxDynamicSharedMemorySize, SMEM_TOTAL);

    convert_x_kernel<<<(M_TOT * K_TOT / 8) / 256, 256>>>(x);
    dequant_kernel<<<(N_TOT * K_TOT / 8) / 256, 256>>>(w, sz);
    gemm_kernel<<<(M_TOT / BM) * (N_TOT / BN), 256, SMEM_TOTAL>>>(bias, out);
}

// round 10
// speedup vs baseline: 1.1562x; 1.0245x over previous
#include <cuda_runtime.h>
#include <cuda_fp16.h>
#include <cstdint>

#define M_TOT 8192
#define N_TOT 11008
#define K_TOT 4096
#define BM 256
#define BN 128
#define BK 64
#define NSTG 4
#define NK (K_TOT / BK)            // 64
#define A_STAGE_B (BM * BK * 2)    // 32768
#define B_STAGE_B (BN * BK * 2)    // 16384
#define STAGE_B   (A_STAGE_B + B_STAGE_B)   // 49152
#define SMEM_TOTAL (NSTG * STAGE_B)         // 196608

// fp16 scratch images (no cudaMalloc allowed)
__device__ __align__(256) __half g_xh[(size_t)M_TOT * K_TOT];   // 64 MB
__device__ __align__(256) __half g_wh[(size_t)N_TOT * K_TOT];   // 88 MB

__device__ __forceinline__ uint32_t sw128(uint32_t o) { return o ^ ((o >> 3) & 0x70u); }

// ---------------- prepass: x fp32 -> fp16 ----------------
__global__ void convert_x_kernel(const float* __restrict__ x) {
    int idx = blockIdx.x * blockDim.x + threadIdx.x;   // one 8-vector
    const float4* src = reinterpret_cast<const float4*>(x) + 2 * (size_t)idx;
    float4 a = src[0], b = src[1];
    __half2 h0 = __floats2half2_rn(a.x, a.y), h1 = __floats2half2_rn(a.z, a.w);
    __half2 h2 = __floats2half2_rn(b.x, b.y), h3 = __floats2half2_rn(b.z, b.w);
    uint4 v;
    v.x = *reinterpret_cast<uint32_t*>(&h0); v.y = *reinterpret_cast<uint32_t*>(&h1);
    v.z = *reinterpret_cast<uint32_t*>(&h2); v.w = *reinterpret_cast<uint32_t*>(&h3);
    reinterpret_cast<uint4*>(g_xh)[idx] = v;
}

// ---------------- prepass: W int32 -> fp16 (w*s+z) ----------------
__global__ void dequant_kernel(const int* __restrict__ w, const float* __restrict__ sz) {
    int idx = blockIdx.x * blockDim.x + threadIdx.x;
    int n  = idx >> 9;                 // 512 vec8 per row of K=4096
    int kk = (idx & 511) << 3;
    int g  = kk >> 7;                  // group of 128
    size_t si = ((size_t)g * N_TOT + n) * 2;
    float s = sz[si], z = sz[si + 1];
    const int4* wp = reinterpret_cast<const int4*>(w + (size_t)n * K_TOT + kk);
    int4 w0 = wp[0], w1 = wp[1];
    __half2 h0 = __floats2half2_rn(fmaf((float)w0.x, s, z), fmaf((float)w0.y, s, z));
    __half2 h1 = __floats2half2_rn(fmaf((float)w0.z, s, z), fmaf((float)w0.w, s, z));
    __half2 h2 = __floats2half2_rn(fmaf((float)w1.x, s, z), fmaf((float)w1.y, s, z));
    __half2 h3 = __floats2half2_rn(fmaf((float)w1.z, s, z), fmaf((float)w1.w, s, z));
    uint4 v;
    v.x = *reinterpret_cast<uint32_t*>(&h0); v.y = *reinterpret_cast<uint32_t*>(&h1);
    v.z = *reinterpret_cast<uint32_t*>(&h2); v.w = *reinterpret_cast<uint32_t*>(&h3);
    reinterpret_cast<uint4*>(g_wh)[idx] = v;
}

// ---------------- helpers ----------------
__device__ __forceinline__ uint32_t smem_u32(const void* p) {
    uint32_t a;
    asm("{ .reg .u64 t; cvta.to.shared.u64 t, %1; cvt.u32.u64 %0, t; }" : "=r"(a) : "l"(p));
    return a;
}
__device__ __forceinline__ void cp_async16(uint32_t s, const void* g) {
    asm volatile("cp.async.cg.shared.global [%0], [%1], 16;" :: "r"(s), "l"(g));
}
__device__ __forceinline__ void cp_commit() { asm volatile("cp.async.commit_group;"); }
template <int N>
__device__ __forceinline__ void cp_wait() { asm volatile("cp.async.wait_group %0;" :: "n"(N)); }

__device__ __forceinline__ void ldsm_x4(uint32_t& r0, uint32_t& r1, uint32_t& r2, uint32_t& r3,
                                        uint32_t addr) {
    asm volatile("ldmatrix.sync.aligned.m8n8.x4.shared.b16 {%0,%1,%2,%3}, [%4];"
                 : "=r"(r0), "=r"(r1), "=r"(r2), "=r"(r3) : "r"(addr));
}
__device__ __forceinline__ void mma16816(float* c, const uint32_t* a, uint32_t b0, uint32_t b1) {
    asm volatile("mma.sync.aligned.m16n8k16.row.col.f32.f16.f16.f32 "
                 "{%0,%1,%2,%3}, {%4,%5,%6,%7}, {%8,%9}, {%0,%1,%2,%3};"
                 : "+f"(c[0]), "+f"(c[1]), "+f"(c[2]), "+f"(c[3])
                 : "r"(a[0]), "r"(a[1]), "r"(a[2]), "r"(a[3]), "r"(b0), "r"(b1));
}
__device__ __forceinline__ void st_cs_v2(float* p, float a, float b) {
    asm volatile("st.global.cs.v2.f32 [%0], {%1,%2};" :: "l"(p), "f"(a), "f"(b) : "memory");
}

// ---------------- GEMM: 256x128 CTA, 512 threads, 16 warps of 64x32 ----------------
__global__ __launch_bounds__(512, 1)
void gemm_kernel(const float* __restrict__ bias, float* __restrict__ out) {
    extern __shared__ __align__(1024) char smem[];
    uint32_t sb = smem_u32(smem);
    int tid = threadIdx.x, wid = tid >> 5, lane = tid & 31;
    // M-fastest grid: A (64 MB) stays L2-resident
    int tile_m = blockIdx.x & 31;          // 32 M tiles of 256
    int tile_n = blockIdx.x >> 5;          // 86 N tiles of 128
    const size_t m0 = (size_t)tile_m * BM, n0 = (size_t)tile_n * BN;

    const __half* agm = g_xh + m0 * K_TOT;
    const __half* bgm = g_wh + n0 * K_TOT;

    int lrow = tid >> 3;            // 0..63 base row
    int lcb  = (tid & 7) * 16;      // byte column within 128B row

    auto load_stage = [&](int kt, int st) {
        uint32_t sa = sb + st * STAGE_B;
        uint32_t sbB = sa + A_STAGE_B;
        const __half* ag = agm + (size_t)kt * BK;
        const __half* bg = bgm + (size_t)kt * BK;
#pragma unroll
        for (int i = 0; i < 4; i++) {      // A: 256 rows, 64 at a time
            int r = lrow + i * 64;
            cp_async16(sa + sw128(r * 128 + lcb), (const char*)(ag + (size_t)r * K_TOT) + lcb);
        }
#pragma unroll
        for (int i = 0; i < 2; i++) {      // B: 128 rows
            int r = lrow + i * 64;
            cp_async16(sbB + sw128(r * 128 + lcb), (const char*)(bg + (size_t)r * K_TOT) + lcb);
        }
        cp_commit();
    };

    // prologue
    for (int st = 0; st < NSTG - 1; st++) load_stage(st, st);

    int wm = wid & 3, wn = wid >> 2;       // 4(m) x 4(n) warps, each 64x32
    float acc[4][4][4];
#pragma unroll
    for (int i = 0; i < 4; i++)
#pragma unroll
        for (int j = 0; j < 4; j++)
#pragma unroll
            for (int t = 0; t < 4; t++) acc[i][j][t] = 0.f;

    // ldmatrix lane address components
    int a_r = wm * 64 + (lane & 15);                       // + mi*16
    int a_c = (lane >> 4) * 16;                            // + s*32
    int b_r = wn * 32 + ((lane >> 4) << 3) + (lane & 7);   // + nh*16
    int b_c = ((lane >> 3) & 1) * 16;                      // + s*32

    for (int kt = 0; kt < NK; kt++) {
        cp_wait<NSTG - 2>();
        __syncthreads();
        if (kt + NSTG - 1 < NK) load_stage(kt + NSTG - 1, (kt + NSTG - 1) % NSTG);
        else cp_commit();   // keep wait_group accounting aligned in the tail

        uint32_t sa = sb + (kt % NSTG) * STAGE_B;
        uint32_t sbB = sa + A_STAGE_B;
#pragma unroll
        for (int s = 0; s < 4; s++) {
            uint32_t af[4][4];
#pragma unroll
            for (int mi = 0; mi < 4; mi++)
                ldsm_x4(af[mi][0], af[mi][1], af[mi][2], af[mi][3],
                        sa + sw128((a_r + mi * 16) * 128 + s * 32 + a_c));
            uint32_t bf[4][2];
#pragma unroll
            for (int nh = 0; nh < 2; nh++) {
                uint32_t r0, r1, r2, r3;
                ldsm_x4(r0, r1, r2, r3,
                        sbB + sw128((b_r + nh * 16) * 128 + s * 32 + b_c));
                bf[nh * 2][0] = r0; bf[nh * 2][1] = r1;
                bf[nh * 2 + 1][0] = r2; bf[nh * 2 + 1][1] = r3;
            }
#pragma unroll
            for (int mi = 0; mi < 4; mi++)
#pragma unroll
                for (int ni = 0; ni < 4; ni++)
                    mma16816(acc[mi][ni], af[mi], bf[ni][0], bf[ni][1]);
        }
        // next iteration's top sync orders compute before slot reuse
    }
    cp_wait<0>();

    // epilogue: c0,c1 @ (row=lane/4, col=(lane%4)*2), c2,c3 @ row+8; streaming stores
    size_t mw = m0 + wm * 64 + (lane >> 2);
    size_t nw = n0 + wn * 32 + (lane & 3) * 2;
#pragma unroll
    for (int mi = 0; mi < 4; mi++) {
#pragma unroll
        for (int ni = 0; ni < 4; ni++) {
            size_t n = nw + ni * 8;
            float b0 = __ldg(bias + n), b1 = __ldg(bias + n + 1);
            float* p0 = out + (mw + mi * 16) * N_TOT + n;
            float* p1 = out + (mw + mi * 16 + 8) * N_TOT + n;
            st_cs_v2(p0, acc[mi][ni][0] + b0, acc[mi][ni][1] + b1);
            st_cs_v2(p1, acc[mi][ni][2] + b0, acc[mi][ni][3] + b1);
        }
    }
}

// ---------------- launch ----------------
extern "C" void kernel_launch(void* const* d_in, const int* in_sizes, int n_in,
                              void* d_out, int out_size) {
    const float* x    = (const float*)d_in[0];
    const int*   w    = (const int*)d_in[1];
    const float* sz   = (const float*)d_in[2];
    const float* bias = (const float*)d_in[3];
    float* out = (float*)d_out;

    cudaFuncSetAttribute(gemm_kernel, cudaFuncAttributeMaxDynamicSharedMemorySize, SMEM_TOTAL);

    convert_x_kernel<<<(M_TOT * K_TOT / 8) / 256, 256>>>(x);
    dequant_kernel<<<(N_TOT * K_TOT / 8) / 256, 256>>>(w, sz);
    gemm_kernel<<<(M_TOT / BM) * (N_TOT / BN), 512, SMEM_TOTAL>>>(bias, out);
}

// round 12
// speedup vs baseline: 1.1771x; 1.0181x over previous
#include <cuda_runtime.h>
#include <cuda_fp16.h>
#include <cstdint>

#define M_TOT 8192
#define N_TOT 11008
#define K_TOT 4096
#define BM 256
#define BN 128
#define BK 64
#define NSTG 4
#define NK (K_TOT / BK)            // 64
#define A_STAGE_B (BM * BK * 2)    // 32768
#define B_STAGE_B (BN * BK * 2)    // 16384
#define STAGE_B   (A_STAGE_B + B_STAGE_B)   // 49152
#define SMEM_TOTAL (NSTG * STAGE_B)         // 196608
#define NSM 148
#define NTILE ((M_TOT / BM) * (N_TOT / BN))  // 2752

// fp16 scratch images (no cudaMalloc allowed)
__device__ __align__(256) __half g_xh[(size_t)M_TOT * K_TOT];   // 64 MB
__device__ __align__(256) __half g_wh[(size_t)N_TOT * K_TOT];   // 88 MB

__device__ __forceinline__ uint32_t sw128(uint32_t o) { return o ^ ((o >> 3) & 0x70u); }

// ---------------- prepass: x fp32 -> fp16 ----------------
__global__ void convert_x_kernel(const float* __restrict__ x) {
    int idx = blockIdx.x * blockDim.x + threadIdx.x;   // one 8-vector
    const float4* src = reinterpret_cast<const float4*>(x) + 2 * (size_t)idx;
    float4 a = src[0], b = src[1];
    __half2 h0 = __floats2half2_rn(a.x, a.y), h1 = __floats2half2_rn(a.z, a.w);
    __half2 h2 = __floats2half2_rn(b.x, b.y), h3 = __floats2half2_rn(b.z, b.w);
    uint4 v;
    v.x = *reinterpret_cast<uint32_t*>(&h0); v.y = *reinterpret_cast<uint32_t*>(&h1);
    v.z = *reinterpret_cast<uint32_t*>(&h2); v.w = *reinterpret_cast<uint32_t*>(&h3);
    reinterpret_cast<uint4*>(g_xh)[idx] = v;
}

// ---------------- prepass: W int32 -> fp16 (w*s+z) ----------------
__global__ void dequant_kernel(const int* __restrict__ w, const float* __restrict__ sz) {
    int idx = blockIdx.x * blockDim.x + threadIdx.x;
    int n  = idx >> 9;                 // 512 vec8 per row of K=4096
    int kk = (idx & 511) << 3;
    int g  = kk >> 7;                  // group of 128
    size_t si = ((size_t)g * N_TOT + n) * 2;
    float s = sz[si], z = sz[si + 1];
    const int4* wp = reinterpret_cast<const int4*>(w + (size_t)n * K_TOT + kk);
    int4 w0 = wp[0], w1 = wp[1];
    __half2 h0 = __floats2half2_rn(fmaf((float)w0.x, s, z), fmaf((float)w0.y, s, z));
    __half2 h1 = __floats2half2_rn(fmaf((float)w0.z, s, z), fmaf((float)w0.w, s, z));
    __half2 h2 = __floats2half2_rn(fmaf((float)w1.x, s, z), fmaf((float)w1.y, s, z));
    __half2 h3 = __floats2half2_rn(fmaf((float)w1.z, s, z), fmaf((float)w1.w, s, z));
    uint4 v;
    v.x = *reinterpret_cast<uint32_t*>(&h0); v.y = *reinterpret_cast<uint32_t*>(&h1);
    v.z = *reinterpret_cast<uint32_t*>(&h2); v.w = *reinterpret_cast<uint32_t*>(&h3);
    reinterpret_cast<uint4*>(g_wh)[idx] = v;
}

// ---------------- helpers ----------------
__device__ __forceinline__ uint32_t smem_u32(const void* p) {
    uint32_t a;
    asm("{ .reg .u64 t; cvta.to.shared.u64 t, %1; cvt.u32.u64 %0, t; }" : "=r"(a) : "l"(p));
    return a;
}
__device__ __forceinline__ void cp_async16(uint32_t s, const void* g) {
    asm volatile("cp.async.cg.shared.global [%0], [%1], 16;" :: "r"(s), "l"(g));
}
__device__ __forceinline__ void cp_commit() { asm volatile("cp.async.commit_group;"); }
template <int N>
__device__ __forceinline__ void cp_wait() { asm volatile("cp.async.wait_group %0;" :: "n"(N)); }

__device__ __forceinline__ void ldsm_x4(uint32_t& r0, uint32_t& r1, uint32_t& r2, uint32_t& r3,
                                        uint32_t addr) {
    asm volatile("ldmatrix.sync.aligned.m8n8.x4.shared.b16 {%0,%1,%2,%3}, [%4];"
                 : "=r"(r0), "=r"(r1), "=r"(r2), "=r"(r3) : "r"(addr));
}
__device__ __forceinline__ void mma16816(float* c, const uint32_t* a, uint32_t b0, uint32_t b1) {
    asm volatile("mma.sync.aligned.m16n8k16.row.col.f32.f16.f16.f32 "
                 "{%0,%1,%2,%3}, {%4,%5,%6,%7}, {%8,%9}, {%0,%1,%2,%3};"
                 : "+f"(c[0]), "+f"(c[1]), "+f"(c[2]), "+f"(c[3])
                 : "r"(a[0]), "r"(a[1]), "r"(a[2]), "r"(a[3]), "r"(b0), "r"(b1));
}
__device__ __forceinline__ void st_cs_v2(float* p, float a, float b) {
    asm volatile("st.global.cs.v2.f32 [%0], {%1,%2};" :: "l"(p), "f"(a), "f"(b) : "memory");
}

// ---------------- GEMM: persistent, 256x128 CTA tile, 512 thr, 16 warps 64x32 ----------------
__global__ __launch_bounds__(512, 1)
void gemm_kernel(const float* __restrict__ bias, float* __restrict__ out) {
    extern __shared__ __align__(1024) char smem[];
    uint32_t sb = smem_u32(smem);
    int tid = threadIdx.x, wid = tid >> 5, lane = tid & 31;
    int bid = blockIdx.x;
    int ntiles_mine = (NTILE - bid + NSM - 1) / NSM;   // tiles bid, bid+148, ...

    int lrow = tid >> 3;            // 0..63 base row
    int lcb  = (tid & 7) * 16;      // byte column within 128B row

    // load one K-stage of global pipeline index g (tile = g/NK, kt = g%NK)
    auto load_stage = [&](int g) {
        int t  = g >> 6;            // / NK
        int kt = g & 63;
        if (t < ntiles_mine) {
            int cl = bid + t * NSM;
            int tm = cl & 31, tn = cl >> 5;          // M-fastest: A stays L2-resident
            const __half* ag = g_xh + ((size_t)tm * BM) * K_TOT + (size_t)kt * BK;
            const __half* bg = g_wh + ((size_t)tn * BN) * K_TOT + (size_t)kt * BK;
            uint32_t sa = sb + (g & (NSTG - 1)) * STAGE_B;
            uint32_t sbB = sa + A_STAGE_B;
#pragma unroll
            for (int i = 0; i < 4; i++) {            // A: 256 rows
                int r = lrow + i * 64;
                cp_async16(sa + sw128(r * 128 + lcb), (const char*)(ag + (size_t)r * K_TOT) + lcb);
            }
#pragma unroll
            for (int i = 0; i < 2; i++) {            // B: 128 rows
                int r = lrow + i * 64;
                cp_async16(sbB + sw128(r * 128 + lcb), (const char*)(bg + (size_t)r * K_TOT) + lcb);
            }
        }
        cp_commit();   // always commit (possibly empty) to keep wait accounting aligned
    };

    // prologue: first NSTG-1 stages
    for (int g = 0; g < NSTG - 1; g++) load_stage(g);

    int wm = wid & 3, wn = wid >> 2;       // 4(m) x 4(n) warps, each 64x32
    // ldmatrix lane address components
    int a_r = wm * 64 + (lane & 15);                       // + mi*16
    int a_c = (lane >> 4) * 16;                            // + s*32
    int b_r = wn * 32 + ((lane >> 4) << 3) + (lane & 7);   // + nh*16
    int b_c = ((lane >> 3) & 1) * 16;                      // + s*32

    for (int t = 0; t < ntiles_mine; t++) {
        float acc[4][4][4];
#pragma unroll
        for (int i = 0; i < 4; i++)
#pragma unroll
            for (int j = 0; j < 4; j++)
#pragma unroll
                for (int c = 0; c < 4; c++) acc[i][j][c] = 0.f;

        int gbase = t * NK;
        for (int kt = 0; kt < NK; kt++) {
            cp_wait<NSTG - 2>();
            __syncthreads();
            load_stage(gbase + kt + NSTG - 1);   // may belong to next tile

            uint32_t sa = sb + (kt & (NSTG - 1)) * STAGE_B;   // NK % NSTG == 0
            uint32_t sbB = sa + A_STAGE_B;
#pragma unroll
            for (int s = 0; s < 4; s++) {
                uint32_t af[4][4];
#pragma unroll
                for (int mi = 0; mi < 4; mi++)
                    ldsm_x4(af[mi][0], af[mi][1], af[mi][2], af[mi][3],
                            sa + sw128((a_r + mi * 16) * 128 + s * 32 + a_c));
                uint32_t bf[4][2];
#pragma unroll
                for (int nh = 0; nh < 2; nh++) {
                    uint32_t r0, r1, r2, r3;
                    ldsm_x4(r0, r1, r2, r3,
                            sbB + sw128((b_r + nh * 16) * 128 + s * 32 + b_c));
                    bf[nh * 2][0] = r0; bf[nh * 2][1] = r1;
                    bf[nh * 2 + 1][0] = r2; bf[nh * 2 + 1][1] = r3;
                }
#pragma unroll
                for (int mi = 0; mi < 4; mi++)
#pragma unroll
                    for (int ni = 0; ni < 4; ni++)
                        mma16816(acc[mi][ni], af[mi], bf[ni][0], bf[ni][1]);
            }
        }

        // epilogue — overlaps with next tile's in-flight loads; stores drain in bg
        int cl = bid + t * NSM;
        size_t m0 = (size_t)(cl & 31) * BM, n0 = (size_t)(cl >> 5) * BN;
        size_t mw = m0 + wm * 64 + (lane >> 2);
        size_t nw = n0 + wn * 32 + (lane & 3) * 2;
#pragma unroll
        for (int mi = 0; mi < 4; mi++) {
#pragma unroll
            for (int ni = 0; ni < 4; ni++) {
                size_t n = nw + ni * 8;
                float b0 = __ldg(bias + n), b1 = __ldg(bias + n + 1);
                float* p0 = out + (mw + mi * 16) * N_TOT + n;
                float* p1 = out + (mw + mi * 16 + 8) * N_TOT + n;
                st_cs_v2(p0, acc[mi][ni][0] + b0, acc[mi][ni][1] + b1);
                st_cs_v2(p1, acc[mi][ni][2] + b0, acc[mi][ni][3] + b1);
            }
        }
    }
}

// ---------------- launch ----------------
extern "C" void kernel_launch(void* const* d_in, const int* in_sizes, int n_in,
                              void* d_out, int out_size) {
    const float* x    = (const float*)d_in[0];
    const int*   w    = (const int*)d_in[1];
    const float* sz   = (const float*)d_in[2];
    const float* bias = (const float*)d_in[3];
    float* out = (float*)d_out;

    cudaFuncSetAttribute(gemm_kernel, cudaFuncAttributeMaxDynamicSharedMemorySize, SMEM_TOTAL);

    convert_x_kernel<<<(M_TOT * K_TOT / 8) / 256, 256>>>(x);
    dequant_kernel<<<(N_TOT * K_TOT / 8) / 256, 256>>>(w, sz);
    gemm_kernel<<<NSM, 512, SMEM_TOTAL>>>(bias, out);
}